// round 15
// baseline (speedup 1.0000x reference)
#include <cuda_runtime.h>
#include <cuda_bf16.h>
#include <math.h>
#include <stdint.h>

// ---------------- problem constants ----------------
#define SSV 4096
#define H1C 768
#define H2C 1280

static constexpr long OUT0_ELEMS = 8L * 4096L * 768L;
static constexpr long OUT1_ELEMS = 8L * 4096L * 1280L;
static constexpr long OUT2_ELEMS = 8L * 2816L;

static constexpr long N40 = OUT0_ELEMS / 4;
static constexpr long N41 = OUT1_ELEMS / 4;
static constexpr long N42 = OUT2_ELEMS / 4;
static constexpr long N4T = N40 + N41 + N42;

static constexpr int NCOMP = 256;     // compute CTAs (2/SM): M64xN128 tile, split-K=2
static constexpr int NCTA  = 296;
static constexpr int NTHR  = 256;
static constexpr long SLOT4 = 1024;   // float4 per copy ticket (16KB)

// per-buffer: Ah[64x32]=4K @0, Al @4096, Wh[128x32]=8K @8192, Wl @16384 -> 24KB
static constexpr int BUFB = 24576;
static constexpr int SMEM_BYTES = 1024 + 3 * BUFB;

// ---------------- device globals ----------------
__device__ float g_bufA[1048576];
__device__ float g_bufB[1048576];
__device__ float g_part[1048576];       // 128 slots x 64x128 fp32 partials
__device__ float g_sum[3 * 8 * 4096];
__device__ float g_ss[3 * 8 * 4096];
__device__ int   g_mbar[640];           // merge barriers [slot*5 + stage]
__device__ int   g_npos[8];
__device__ int   g_cbar[40];            // chain stage barriers [chain*5 + stage]
__device__ int   g_gbar;
__device__ int   g_ticket;

__device__ __forceinline__ size_t ch_off(int c) {
    return (c < 4) ? (size_t)c * 128 * 768
                   : (size_t)4 * 128 * 768 + (size_t)(c - 4) * 128 * 1280;
}

struct Params {
    const float* extra;
    const float* f1w[2]; const float* f1b[2];
    const float* gg[2];  const float* gb[2];
    const float* bw[2];  const float* bb[2];
    const float* ow[2];  const float* ob[2];
    const float* e0; const float* e1; const float* e2;
    float* out;
};

// ---------------- helpers ----------------
__device__ __forceinline__ uint32_t s2u(const void* p) {
    uint32_t a;
    asm("{ .reg .u64 t; cvta.to.shared.u64 t, %1; cvt.u32.u64 %0, t; }" : "=r"(a) : "l"(p));
    return a;
}
__device__ __forceinline__ uint32_t swz64(uint32_t o) { return o ^ ((o >> 3) & 0x30); }

__device__ __forceinline__ void ldsm4(uint32_t* r, uint32_t a) {
    asm volatile("ldmatrix.sync.aligned.m8n8.x4.shared.b16 {%0,%1,%2,%3}, [%4];"
                 : "=r"(r[0]), "=r"(r[1]), "=r"(r[2]), "=r"(r[3]) : "r"(a));
}
__device__ __forceinline__ void ldsm2(uint32_t* r, uint32_t a) {
    asm volatile("ldmatrix.sync.aligned.m8n8.x2.shared.b16 {%0,%1}, [%2];"
                 : "=r"(r[0]), "=r"(r[1]) : "r"(a));
}
__device__ __forceinline__ void mma16816(float* d, const uint32_t* a, const uint32_t* b) {
    asm volatile(
        "mma.sync.aligned.m16n8k16.row.col.f32.bf16.bf16.f32 "
        "{%0,%1,%2,%3}, {%4,%5,%6,%7}, {%8,%9}, {%0,%1,%2,%3};"
        : "+f"(d[0]), "+f"(d[1]), "+f"(d[2]), "+f"(d[3])
        : "r"(a[0]), "r"(a[1]), "r"(a[2]), "r"(a[3]), "r"(b[0]), "r"(b[1]));
}

// round-to-nearest hi/lo bf16 split (R9-proven)
__device__ __forceinline__ void split2(float x0, float x1, uint32_t& h, uint32_t& l) {
    __nv_bfloat16 h0 = __float2bfloat16(x0);
    __nv_bfloat16 h1 = __float2bfloat16(x1);
    __nv_bfloat16 l0 = __float2bfloat16(x0 - __bfloat162float(h0));
    __nv_bfloat16 l1 = __float2bfloat16(x1 - __bfloat162float(h1));
    uint16_t hb0 = *reinterpret_cast<uint16_t*>(&h0);
    uint16_t hb1 = *reinterpret_cast<uint16_t*>(&h1);
    uint16_t lb0 = *reinterpret_cast<uint16_t*>(&l0);
    uint16_t lb1 = *reinterpret_cast<uint16_t*>(&l1);
    h = (uint32_t)hb0 | ((uint32_t)hb1 << 16);
    l = (uint32_t)lb0 | ((uint32_t)lb1 << 16);
}

__device__ __forceinline__ float4 ldcg4(const float* p) { return __ldcg((const float4*)p); }
__device__ __forceinline__ float2 ldcg2(const float* p) { return __ldcg((const float2*)p); }

// ---------------- barrier (fence + arrive + spin + fence) ----------------
__device__ __forceinline__ void barrier_on(int* cnt, int target) {
    __threadfence();
    __syncthreads();
    if (threadIdx.x == 0) {
        atomicAdd(cnt, 1);
        while (*(volatile int*)cnt < target) __nanosleep(32);
        __threadfence();
    }
    __syncthreads();
}

// ---------------- pipelined copy ticket: split load / store ----------------
struct CopyTk {
    float4 d[4];
    long i0;
    int nval;   // number of valid float4 (0..4)
    float4* o;
};
__device__ __forceinline__ void copy_load(const Params& p, long tk, CopyTk& ct) {
    long base = tk * SLOT4;
    ct.nval = 0;
    ct.o = (float4*)p.out;
    if (base >= N4T) return;
    ct.i0 = base + threadIdx.x * 4;
    const float4* src; long off;
    if (base < N40)            { src = (const float4*)p.e0; off = ct.i0; }
    else if (base < N40 + N41) { src = (const float4*)p.e1; off = ct.i0 - N40; }
    else                       { src = (const float4*)p.e2; off = ct.i0 - N40 - N41; }
    #pragma unroll
    for (int e = 0; e < 4; e++) {
        if (ct.i0 + e < N4T) {
            ct.d[e] = __ldcg(src + off + e);
            ct.nval = e + 1;
        }
    }
}
__device__ __forceinline__ void copy_store(CopyTk& ct) {
    #pragma unroll
    for (int e = 0; e < 4; e++)
        if (e < ct.nval) ct.o[ct.i0 + e] = ct.d[e];
}

// full slot copy (for dedicated CTAs / drain)
__device__ __forceinline__ void copy_slot(const Params& p, long tk) {
    CopyTk ct;
    copy_load(p, tk, ct);
    copy_store(ct);
}

// ---------------- GEMM stage: M64xN128, split-K=2, bf16x3, triple-buffered ----------------
// Copy ticket pipelined across the chunk body: LDG at top, STG at bottom.
template <int MODE, bool STATS>
__device__ void run_stage(char* sm, uint32_t sb,
                          const float* __restrict__ A, float* __restrict__ O,
                          const float* __restrict__ W, const float* __restrict__ bias,
                          const float* __restrict__ gng, const float* __restrict__ gnb,
                          const float* __restrict__ rs_s, const float* __restrict__ rs_q,
                          float* __restrict__ ws_s, float* __restrict__ ws_q,
                          int K, int Khalf, int kh0, int hid, int n0, int magic,
                          float inv_gs, float* __restrict__ part, int* mbar,
                          bool primary, const Params& pp, int* s_t2) {
    int tid = threadIdx.x, lane = tid & 31, wid = tid >> 5;
    int mbase = (wid & 1) * 32, nbase = (wid >> 1) * 32;
    int nch = Khalf >> 5;

    // A loader: 64 rows, 4 threads/row, 8 cols each
    int rowa = tid >> 2, ca8 = (tid & 3) * 8;
    // W loader: 128 rows, 2 threads/row, 16 cols each
    int roww = tid >> 1, cw16 = (tid & 1) * 16;

    const float* Arow = A + (size_t)rowa * K + kh0 + ca8;
    const float* Wrow = W + (size_t)(n0 + roww) * K + kh0 + cw16;
    uint32_t soffA  = swz64((uint32_t)rowa * 64 + (tid & 3) * 16);
    uint32_t soffW0 = swz64((uint32_t)roww * 64 + (tid & 1) * 32);
    uint32_t soffW1 = swz64((uint32_t)roww * 64 + (tid & 1) * 32 + 16);

    float acc[2][4][4];
    #pragma unroll
    for (int i = 0; i < 2; i++)
        #pragma unroll
        for (int j = 0; j < 4; j++)
            #pragma unroll
            for (int e = 0; e < 4; e++) acc[i][j][e] = 0.f;

    float4 ra[2], rw[4];

    auto convert_to = [&](char* buf, int cc) {
        float xs[8] = {ra[0].x, ra[0].y, ra[0].z, ra[0].w,
                       ra[1].x, ra[1].y, ra[1].z, ra[1].w};
        if (MODE == 1) {
            int k = kh0 + cc * 32 + ca8;
            int g = (k * magic) >> 16;
            float s = __ldg(rs_s + rowa * 32 + g);
            float q = __ldg(rs_q + rowa * 32 + g);
            float mean = s * inv_gs;
            float var = q * inv_gs - mean * mean;
            float rstd = rsqrtf(fmaxf(var, 0.f) + 1e-5f);
            #pragma unroll
            for (int e = 0; e < 8; e++)
                xs[e] = (xs[e] - mean) * rstd * __ldg(gng + k + e) + __ldg(gnb + k + e);
        }
        uint4 hv, lv;
        split2(xs[0], xs[1], hv.x, lv.x);
        split2(xs[2], xs[3], hv.y, lv.y);
        split2(xs[4], xs[5], hv.z, lv.z);
        split2(xs[6], xs[7], hv.w, lv.w);
        *(uint4*)(buf + soffA)        = hv;
        *(uint4*)(buf + 4096 + soffA) = lv;

        uint4 hw, lw;
        split2(rw[0].x, rw[0].y, hw.x, lw.x);
        split2(rw[0].z, rw[0].w, hw.y, lw.y);
        split2(rw[1].x, rw[1].y, hw.z, lw.z);
        split2(rw[1].z, rw[1].w, hw.w, lw.w);
        *(uint4*)(buf + 8192 + soffW0)  = hw;
        *(uint4*)(buf + 16384 + soffW0) = lw;
        split2(rw[2].x, rw[2].y, hw.x, lw.x);
        split2(rw[2].z, rw[2].w, hw.y, lw.y);
        split2(rw[3].x, rw[3].y, hw.z, lw.z);
        split2(rw[3].z, rw[3].w, hw.w, lw.w);
        *(uint4*)(buf + 8192 + soffW1)  = hw;
        *(uint4*)(buf + 16384 + soffW1) = lw;
    };
    auto load_regs = [&](int cc) {
        int kb = cc * 32;
        ra[0] = ldcg4(Arow + kb);
        ra[1] = ldcg4(Arow + kb + 4);
        rw[0] = __ldg((const float4*)(Wrow + kb));
        rw[1] = __ldg((const float4*)(Wrow + kb + 4));
        rw[2] = __ldg((const float4*)(Wrow + kb + 8));
        rw[3] = __ldg((const float4*)(Wrow + kb + 12));
    };

    load_regs(0);
    convert_to(sm, 0);
    load_regs(1);
    if (tid == 0) s_t2[0] = atomicAdd(&g_ticket, 1);   // ticket for chunk 0
    __syncthreads();

    for (int c = 0; c < nch; c++) {
        // issue this chunk's copy loads EARLY (latency hides under convert+MMA)
        CopyTk ct;
        copy_load(pp, (long)s_t2[c & 1], ct);
        // grab next chunk's ticket (broadcast via end-of-chunk syncthreads)
        if (tid == 0 && c + 1 < nch) s_t2[(c + 1) & 1] = atomicAdd(&g_ticket, 1);

        if (c + 1 < nch) {
            convert_to(sm + ((c + 1) % 3) * BUFB, c + 1);
            if (c + 2 < nch) load_regs(c + 2);
        }
        uint32_t bu = sb + (c % 3) * BUFB;
        #pragma unroll
        for (int ks = 0; ks < 2; ks++) {
            uint32_t ah[2][4], al[2][4], bh[4][2], bl[4][2];
            #pragma unroll
            for (int mt = 0; mt < 2; mt++) {
                uint32_t off = (uint32_t)(mbase + mt * 16 + (lane & 15)) * 64
                             + ks * 32 + (lane >> 4) * 16;
                ldsm4(ah[mt], bu + swz64(off));
                ldsm4(al[mt], bu + 4096 + swz64(off));
            }
            #pragma unroll
            for (int nt = 0; nt < 4; nt++) {
                uint32_t off = (uint32_t)(nbase + nt * 8 + (lane & 7)) * 64
                             + ks * 32 + ((lane >> 3) & 1) * 16;
                ldsm2(bh[nt], bu + 8192 + swz64(off));
                ldsm2(bl[nt], bu + 16384 + swz64(off));
            }
            #pragma unroll
            for (int mt = 0; mt < 2; mt++)
                #pragma unroll
                for (int nt = 0; nt < 4; nt++) {
                    mma16816(acc[mt][nt], ah[mt], bh[nt]);
                    mma16816(acc[mt][nt], al[mt], bh[nt]);
                    mma16816(acc[mt][nt], ah[mt], bl[nt]);
                }
        }
        // copy stores: loads have had the whole chunk body to land
        copy_store(ct);
        __syncthreads();
    }

    // secondary publishes its partial before the rendezvous
    if (!primary) {
        #pragma unroll
        for (int mt = 0; mt < 2; mt++)
            #pragma unroll
            for (int nt = 0; nt < 4; nt++) {
                int cl = nbase + nt * 8 + (lane & 3) * 2;
                #pragma unroll
                for (int h = 0; h < 2; h++) {
                    int r = mbase + mt * 16 + (lane >> 2) + h * 8;
                    float2 v = {acc[mt][nt][h * 2], acc[mt][nt][h * 2 + 1]};
                    *(float2*)(part + r * 128 + cl) = v;
                }
            }
    }

    barrier_on(mbar, 2);
    if (!primary) return;

    #pragma unroll
    for (int mt = 0; mt < 2; mt++)
        #pragma unroll
        for (int nt = 0; nt < 4; nt++) {
            int cl = nbase + nt * 8 + (lane & 3) * 2;
            int cc = n0 + cl;
            int gblk = ((n0 + nbase + nt * 8) * magic) >> 16;
            #pragma unroll
            for (int h = 0; h < 2; h++) {
                int r = mbase + mt * 16 + (lane >> 2) + h * 8;
                float2 pv = ldcg2(part + r * 128 + cl);
                float v0 = acc[mt][nt][h * 2 + 0] + pv.x + __ldg(bias + cc);
                float v1 = acc[mt][nt][h * 2 + 1] + pv.y + __ldg(bias + cc + 1);
                if (MODE <= 1) {
                    v0 = v0 / (1.f + __expf(-v0));
                    v1 = v1 / (1.f + __expf(-v1));
                }
                if (MODE == 1) {
                    float2 rv = ldcg2(A + (size_t)r * hid + cc);
                    v0 += rv.x; v1 += rv.y;
                }
                float2 o2 = {v0, v1};
                *(float2*)(O + (size_t)r * hid + cc) = o2;
                if (STATS) {
                    float ps = v0 + v1;
                    float q = v0 * v0 + v1 * v1;
                    ps += __shfl_xor_sync(0xffffffff, ps, 1);
                    q  += __shfl_xor_sync(0xffffffff, q, 1);
                    ps += __shfl_xor_sync(0xffffffff, ps, 2);
                    q  += __shfl_xor_sync(0xffffffff, q, 2);
                    if ((lane & 3) == 0) {
                        atomicAdd(ws_s + r * 32 + gblk, ps);
                        atomicAdd(ws_q + r * 32 + gblk, q);
                    }
                }
            }
        }
}

// ---------------- ticketed copy (dedicated CTAs + post-compute drain) ----------------
__device__ void copy_work(const Params& p, int* s_ticket) {
    while (true) {
        if (threadIdx.x == 0) *s_ticket = atomicAdd(&g_ticket, 4);
        __syncthreads();
        long t0 = *s_ticket;
        __syncthreads();
        if (t0 * SLOT4 >= N4T) break;
        // pipeline pairs: load 2 tickets, store 2 tickets
        #pragma unroll
        for (int j = 0; j < 4; j += 2) {
            CopyTk a, b;
            copy_load(p, t0 + j, a);
            copy_load(p, t0 + j + 1, b);
            copy_store(a);
            copy_store(b);
        }
    }
}

// ---------------- scatter ----------------
__device__ void scatter_all(float* __restrict__ out, int cid) {
    for (int c = cid; c < 80; c += NCTA) {
        int te = c / 40, rem = c % 40, b = rem / 5, r = rem % 5;
        int np = g_npos[b];
        if (!np) continue;
        int hid = te ? H2C : H1C;
        int t = (r < 4) ? r : 3;
        int chain = te * 4 + t;
        const float* tok = g_bufA + ch_off(chain);
        float* o = te ? out + OUT0_ELEMS + (size_t)b * SSV * H2C
                      : out + (size_t)b * SSV * H1C;
        int h4 = hid >> 2, tot = np * h4;
        for (int e = threadIdx.x; e < tot; e += NTHR) {
            int i = e / h4, c4 = e % h4;
            int s = (r < 4) ? (SSV - 1 - r * np - i) : (SSV - 5 * np + i);
            float4 v = __ldcg((const float4*)(tok + (size_t)(b * 16 + i) * hid) + c4);
            ((float4*)(o + (size_t)s * hid))[c4] = v;
        }
    }
}

// ---------------- kernels ----------------
__global__ void reset_kernel() {
    int idx = blockIdx.x * 256 + threadIdx.x;
    if (idx < 3 * 8 * 4096) { g_sum[idx] = 0.f; g_ss[idx] = 0.f; }
    if (idx < 640) g_mbar[idx] = 0;
    if (idx < 40) g_cbar[idx] = 0;
    if (idx == 40) { g_gbar = 0; g_ticket = 0; }
}

__global__ void __launch_bounds__(NTHR, 2) mega_kernel(Params p) {
    extern __shared__ char smraw[];
    __shared__ int s_ticket;
    __shared__ int s_t2[2];
    int cid = blockIdx.x, tid = threadIdx.x;

    if (cid >= NCOMP) {
        copy_work(p, &s_ticket);
        barrier_on(&g_gbar, NCTA);
        scatter_all(p.out, cid);
        return;
    }

    uint32_t sb0 = s2u(smraw);
    uint32_t sb = (sb0 + 1023) & ~1023u;
    char* sm = smraw + (sb - sb0);
    int lane = tid & 31, wid = tid >> 5;

    if (cid < 8 && wid == 0) {
        int b = cid, cnt = 0;
        for (int s = 0; s < 16; s++) {
            float v = 0.f;
            #pragma unroll
            for (int j = 0; j < 8; j++)
                v += fabsf(p.extra[((size_t)b * 16 + s) * 704 + 448 + lane * 8 + j]);
            #pragma unroll
            for (int o = 16; o > 0; o >>= 1)
                v += __shfl_xor_sync(0xffffffff, v, o);
            if (v > 1e-6f) cnt++;
        }
        if (lane == 0) g_npos[b] = cnt;
    }

    // decode: cid<160: te2 chains (4 x 40: kh x mt x nt = 2x2x10)
    //         160<=cid<256: te1 chains (4 x 24: 2x2x6)
    int chain, nt, mt, kh, hid, nc_chain, slot;
    if (cid < 160) {
        chain = 4 + cid / 40;
        int r = cid % 40;
        kh = r / 20; int rr = r % 20;
        mt = rr / 10; nt = rr % 10;
        hid = 1280; nc_chain = 40;
        slot = 48 + (chain - 4) * 20 + mt * 10 + nt;
    } else {
        int c2 = cid - 160;
        chain = c2 / 24;
        int r = c2 % 24;
        kh = r / 12; int rr = r % 12;
        mt = rr / 6; nt = rr % 6;
        hid = 768; nc_chain = 24;
        slot = chain * 12 + mt * 6 + nt;
    }
    int te = chain >> 2, t = chain & 3;
    int n0 = nt * 128, m0 = mt * 64;   // N-tile stride is 128 (R13-proven mapping)
    int magic = (hid == 768) ? 2731 : 1639;
    float inv_gs = 1.f / (float)(hid >> 5);
    size_t co = ch_off(chain);
    bool primary = (kh == 0);
    float* part = g_part + (size_t)slot * 8192;
    int* mb = g_mbar + slot * 5;
    int* cb = g_cbar + chain * 5;

    float* st_s0 = g_sum + (0 * 8 + chain) * 4096 + m0 * 32;
    float* st_q0 = g_ss  + (0 * 8 + chain) * 4096 + m0 * 32;
    float* st_s1 = g_sum + (1 * 8 + chain) * 4096 + m0 * 32;
    float* st_q1 = g_ss  + (1 * 8 + chain) * 4096 + m0 * 32;
    float* st_s2 = g_sum + (2 * 8 + chain) * 4096 + m0 * 32;
    float* st_q2 = g_ss  + (2 * 8 + chain) * 4096 + m0 * 32;

    int Kh_fc1 = 352, Kh = hid >> 1;
    float* bA = g_bufA + co + (size_t)m0 * hid;
    float* bB = g_bufB + co + (size_t)m0 * hid;

    run_stage<0, true>(sm, sb, p.extra + (size_t)m0 * 704, bA,
                       p.f1w[te] + (size_t)t * hid * 704, p.f1b[te] + t * hid,
                       nullptr, nullptr, nullptr, nullptr, st_s0, st_q0,
                       704, Kh_fc1, kh * Kh_fc1, hid, n0, magic, inv_gs,
                       part, mb + 0, primary, p, s_t2);
    barrier_on(cb + 0, nc_chain);

    {
        size_t wo = (size_t)(t * 3 + 0) * hid;
        run_stage<1, true>(sm, sb, bA, bB,
                           p.bw[te] + wo * hid, p.bb[te] + wo,
                           p.gg[te] + wo, p.gb[te] + wo, st_s0, st_q0, st_s1, st_q1,
                           hid, Kh, kh * Kh, hid, n0, magic, inv_gs,
                           part, mb + 1, primary, p, s_t2);
    }
    barrier_on(cb + 1, nc_chain);

    {
        size_t wo = (size_t)(t * 3 + 1) * hid;
        run_stage<1, true>(sm, sb, bB, bA,
                           p.bw[te] + wo * hid, p.bb[te] + wo,
                           p.gg[te] + wo, p.gb[te] + wo, st_s1, st_q1, st_s2, st_q2,
                           hid, Kh, kh * Kh, hid, n0, magic, inv_gs,
                           part, mb + 2, primary, p, s_t2);
    }
    barrier_on(cb + 2, nc_chain);

    {
        size_t wo = (size_t)(t * 3 + 2) * hid;
        run_stage<1, false>(sm, sb, bA, bB,
                            p.bw[te] + wo * hid, p.bb[te] + wo,
                            p.gg[te] + wo, p.gb[te] + wo, st_s2, st_q2, nullptr, nullptr,
                            hid, Kh, kh * Kh, hid, n0, magic, inv_gs,
                            part, mb + 3, primary, p, s_t2);
    }
    barrier_on(cb + 3, nc_chain);

    run_stage<2, false>(sm, sb, bB, bA,
                        p.ow[te] + (size_t)t * hid * hid, p.ob[te] + t * hid,
                        nullptr, nullptr, nullptr, nullptr, nullptr, nullptr,
                        hid, Kh, kh * Kh, hid, n0, magic, inv_gs,
                        part, mb + 4, primary, p, s_t2);

    copy_work(p, &s_ticket);
    barrier_on(&g_gbar, NCTA);
    scatter_all(p.out, cid);
}

// ---------------- launch ----------------
extern "C" void kernel_launch(void* const* d_in, const int* in_sizes, int n_in,
                              void* d_out, int out_size) {
    Params p;
    p.e0    = (const float*)d_in[0];
    p.e1    = (const float*)d_in[1];
    p.e2    = (const float*)d_in[2];
    p.extra = (const float*)d_in[3];
    p.f1w[0] = (const float*)d_in[4];  p.f1b[0] = (const float*)d_in[5];
    p.gg[0]  = (const float*)d_in[6];  p.gb[0]  = (const float*)d_in[7];
    p.bw[0]  = (const float*)d_in[8];  p.bb[0]  = (const float*)d_in[9];
    p.ow[0]  = (const float*)d_in[10]; p.ob[0]  = (const float*)d_in[11];
    p.f1w[1] = (const float*)d_in[12]; p.f1b[1] = (const float*)d_in[13];
    p.gg[1]  = (const float*)d_in[14]; p.gb[1]  = (const float*)d_in[15];
    p.bw[1]  = (const float*)d_in[16]; p.bb[1]  = (const float*)d_in[17];
    p.ow[1]  = (const float*)d_in[18]; p.ob[1]  = (const float*)d_in[19];
    p.out = (float*)d_out;

    cudaFuncSetAttribute(mega_kernel, cudaFuncAttributeMaxDynamicSharedMemorySize, SMEM_BYTES);

    reset_kernel<<<(3 * 8 * 4096 + 255) / 256, 256>>>();
    mega_kernel<<<NCTA, NTHR, SMEM_BYTES>>>(p);
}

// round 17
// speedup vs baseline: 1.0093x; 1.0093x over previous
#include <cuda_runtime.h>
#include <cuda_bf16.h>
#include <math.h>
#include <stdint.h>

// ---------------- problem constants ----------------
#define SSV 4096
#define H1C 768
#define H2C 1280

static constexpr long OUT0_ELEMS = 8L * 4096L * 768L;
static constexpr long OUT1_ELEMS = 8L * 4096L * 1280L;
static constexpr long OUT2_ELEMS = 8L * 2816L;

static constexpr long N40 = OUT0_ELEMS / 4;
static constexpr long N41 = OUT1_ELEMS / 4;
static constexpr long N42 = OUT2_ELEMS / 4;
static constexpr long N4T = N40 + N41 + N42;

static constexpr int NCOMP = 256;     // compute CTAs (2/SM): M64xN128 tile, split-K=2
static constexpr int NCTA  = 296;
static constexpr int NTHR  = 256;
static constexpr long SLOT4 = 1024;   // float4 per copy ticket (16KB)

// per-buffer: Ah[64x32]=4K @0, Al @4096, Wh[128x32]=8K @8192, Wl @16384 -> 24KB
static constexpr int BUFB = 24576;
static constexpr int SMEM_BYTES = 1024 + 3 * BUFB;

// ---------------- device globals ----------------
__device__ float g_bufA[1048576];
__device__ float g_bufB[1048576];
__device__ float g_part[1048576];       // 128 slots x 64x128 fp32 partials
__device__ float g_sum[3 * 8 * 4096];
__device__ float g_ss[3 * 8 * 4096];
__device__ int   g_mbar[640];           // merge barriers [slot*5 + stage]
__device__ int   g_npos[8];
__device__ int   g_cbar[40];            // chain stage barriers [chain*5 + stage]
__device__ int   g_gbar;
__device__ int   g_ticket;

__device__ __forceinline__ size_t ch_off(int c) {
    return (c < 4) ? (size_t)c * 128 * 768
                   : (size_t)4 * 128 * 768 + (size_t)(c - 4) * 128 * 1280;
}

struct Params {
    const float* extra;
    const float* f1w[2]; const float* f1b[2];
    const float* gg[2];  const float* gb[2];
    const float* bw[2];  const float* bb[2];
    const float* ow[2];  const float* ob[2];
    const float* e0; const float* e1; const float* e2;
    float* out;
};

// ---------------- helpers ----------------
__device__ __forceinline__ uint32_t s2u(const void* p) {
    uint32_t a;
    asm("{ .reg .u64 t; cvta.to.shared.u64 t, %1; cvt.u32.u64 %0, t; }" : "=r"(a) : "l"(p));
    return a;
}
__device__ __forceinline__ uint32_t swz64(uint32_t o) { return o ^ ((o >> 3) & 0x30); }

__device__ __forceinline__ void ldsm4(uint32_t* r, uint32_t a) {
    asm volatile("ldmatrix.sync.aligned.m8n8.x4.shared.b16 {%0,%1,%2,%3}, [%4];"
                 : "=r"(r[0]), "=r"(r[1]), "=r"(r[2]), "=r"(r[3]) : "r"(a));
}
__device__ __forceinline__ void ldsm2(uint32_t* r, uint32_t a) {
    asm volatile("ldmatrix.sync.aligned.m8n8.x2.shared.b16 {%0,%1}, [%2];"
                 : "=r"(r[0]), "=r"(r[1]) : "r"(a));
}
__device__ __forceinline__ void mma16816(float* d, const uint32_t* a, const uint32_t* b) {
    asm volatile(
        "mma.sync.aligned.m16n8k16.row.col.f32.bf16.bf16.f32 "
        "{%0,%1,%2,%3}, {%4,%5,%6,%7}, {%8,%9}, {%0,%1,%2,%3};"
        : "+f"(d[0]), "+f"(d[1]), "+f"(d[2]), "+f"(d[3])
        : "r"(a[0]), "r"(a[1]), "r"(a[2]), "r"(a[3]), "r"(b[0]), "r"(b[1]));
}

// round-to-nearest hi/lo bf16 split (R9-proven)
__device__ __forceinline__ void split2(float x0, float x1, uint32_t& h, uint32_t& l) {
    __nv_bfloat16 h0 = __float2bfloat16(x0);
    __nv_bfloat16 h1 = __float2bfloat16(x1);
    __nv_bfloat16 l0 = __float2bfloat16(x0 - __bfloat162float(h0));
    __nv_bfloat16 l1 = __float2bfloat16(x1 - __bfloat162float(h1));
    uint16_t hb0 = *reinterpret_cast<uint16_t*>(&h0);
    uint16_t hb1 = *reinterpret_cast<uint16_t*>(&h1);
    uint16_t lb0 = *reinterpret_cast<uint16_t*>(&l0);
    uint16_t lb1 = *reinterpret_cast<uint16_t*>(&l1);
    h = (uint32_t)hb0 | ((uint32_t)hb1 << 16);
    l = (uint32_t)lb0 | ((uint32_t)lb1 << 16);
}

__device__ __forceinline__ float4 ldcg4(const float* p) { return __ldcg((const float4*)p); }
__device__ __forceinline__ float2 ldcg2(const float* p) { return __ldcg((const float2*)p); }

// ---------------- barrier (fence + arrive + spin + fence) ----------------
__device__ __forceinline__ void barrier_on(int* cnt, int target) {
    __threadfence();
    __syncthreads();
    if (threadIdx.x == 0) {
        atomicAdd(cnt, 1);
        while (*(volatile int*)cnt < target) __nanosleep(32);
        __threadfence();
    }
    __syncthreads();
}

// ---------------- pipelined copy ticket: split load / store ----------------
struct CopyTk {
    float4 d[4];
    long i0;
    int nval;   // number of valid float4 (0..4)
    float4* o;
};
__device__ __forceinline__ void copy_load(const Params& p, long tk, CopyTk& ct) {
    long base = tk * SLOT4;
    ct.nval = 0;
    ct.o = (float4*)p.out;
    if (base >= N4T) return;
    ct.i0 = base + threadIdx.x * 4;
    const float4* src; long off;
    if (base < N40)            { src = (const float4*)p.e0; off = ct.i0; }
    else if (base < N40 + N41) { src = (const float4*)p.e1; off = ct.i0 - N40; }
    else                       { src = (const float4*)p.e2; off = ct.i0 - N40 - N41; }
    #pragma unroll
    for (int e = 0; e < 4; e++) {
        if (ct.i0 + e < N4T) {
            ct.d[e] = __ldcg(src + off + e);
            ct.nval = e + 1;
        }
    }
}
__device__ __forceinline__ void copy_store(CopyTk& ct) {
    #pragma unroll
    for (int e = 0; e < 4; e++)
        if (e < ct.nval) ct.o[ct.i0 + e] = ct.d[e];
}

// full slot copy (for dedicated CTAs / drain)
__device__ __forceinline__ void copy_slot(const Params& p, long tk) {
    CopyTk ct;
    copy_load(p, tk, ct);
    copy_store(ct);
}

// ---------------- GEMM stage: M64xN128, split-K=2, bf16x3, triple-buffered ----------------
// Copy ticket pipelined across the MMA section only (short reg live range).
template <int MODE, bool STATS>
__device__ void run_stage(char* sm, uint32_t sb,
                          const float* __restrict__ A, float* __restrict__ O,
                          const float* __restrict__ W, const float* __restrict__ bias,
                          const float* __restrict__ gng, const float* __restrict__ gnb,
                          const float* __restrict__ rs_s, const float* __restrict__ rs_q,
                          float* __restrict__ ws_s, float* __restrict__ ws_q,
                          int K, int Khalf, int kh0, int hid, int n0, int magic,
                          float inv_gs, float* __restrict__ part, int* mbar,
                          bool primary, const Params& pp, int* s_t2) {
    int tid = threadIdx.x, lane = tid & 31, wid = tid >> 5;
    int mbase = (wid & 1) * 32, nbase = (wid >> 1) * 32;
    int nch = Khalf >> 5;

    // A loader: 64 rows, 4 threads/row, 8 cols each
    int rowa = tid >> 2, ca8 = (tid & 3) * 8;
    // W loader: 128 rows, 2 threads/row, 16 cols each
    int roww = tid >> 1, cw16 = (tid & 1) * 16;

    const float* Arow = A + (size_t)rowa * K + kh0 + ca8;
    const float* Wrow = W + (size_t)(n0 + roww) * K + kh0 + cw16;
    uint32_t soffA  = swz64((uint32_t)rowa * 64 + (tid & 3) * 16);
    uint32_t soffW0 = swz64((uint32_t)roww * 64 + (tid & 1) * 32);
    uint32_t soffW1 = swz64((uint32_t)roww * 64 + (tid & 1) * 32 + 16);

    float acc[2][4][4];
    #pragma unroll
    for (int i = 0; i < 2; i++)
        #pragma unroll
        for (int j = 0; j < 4; j++)
            #pragma unroll
            for (int e = 0; e < 4; e++) acc[i][j][e] = 0.f;

    float4 ra[2], rw[4];

    auto convert_to = [&](char* buf, int cc) {
        float xs[8] = {ra[0].x, ra[0].y, ra[0].z, ra[0].w,
                       ra[1].x, ra[1].y, ra[1].z, ra[1].w};
        if (MODE == 1) {
            int k = kh0 + cc * 32 + ca8;
            int g = (k * magic) >> 16;
            float s = __ldg(rs_s + rowa * 32 + g);
            float q = __ldg(rs_q + rowa * 32 + g);
            float mean = s * inv_gs;
            float var = q * inv_gs - mean * mean;
            float rstd = rsqrtf(fmaxf(var, 0.f) + 1e-5f);
            #pragma unroll
            for (int e = 0; e < 8; e++)
                xs[e] = (xs[e] - mean) * rstd * __ldg(gng + k + e) + __ldg(gnb + k + e);
        }
        uint4 hv, lv;
        split2(xs[0], xs[1], hv.x, lv.x);
        split2(xs[2], xs[3], hv.y, lv.y);
        split2(xs[4], xs[5], hv.z, lv.z);
        split2(xs[6], xs[7], hv.w, lv.w);
        *(uint4*)(buf + soffA)        = hv;
        *(uint4*)(buf + 4096 + soffA) = lv;

        uint4 hw, lw;
        split2(rw[0].x, rw[0].y, hw.x, lw.x);
        split2(rw[0].z, rw[0].w, hw.y, lw.y);
        split2(rw[1].x, rw[1].y, hw.z, lw.z);
        split2(rw[1].z, rw[1].w, hw.w, lw.w);
        *(uint4*)(buf + 8192 + soffW0)  = hw;
        *(uint4*)(buf + 16384 + soffW0) = lw;
        split2(rw[2].x, rw[2].y, hw.x, lw.x);
        split2(rw[2].z, rw[2].w, hw.y, lw.y);
        split2(rw[3].x, rw[3].y, hw.z, lw.z);
        split2(rw[3].z, rw[3].w, hw.w, lw.w);
        *(uint4*)(buf + 8192 + soffW1)  = hw;
        *(uint4*)(buf + 16384 + soffW1) = lw;
    };
    auto load_regs = [&](int cc) {
        int kb = cc * 32;
        ra[0] = ldcg4(Arow + kb);
        ra[1] = ldcg4(Arow + kb + 4);
        rw[0] = __ldg((const float4*)(Wrow + kb));
        rw[1] = __ldg((const float4*)(Wrow + kb + 4));
        rw[2] = __ldg((const float4*)(Wrow + kb + 8));
        rw[3] = __ldg((const float4*)(Wrow + kb + 12));
    };

    load_regs(0);
    convert_to(sm, 0);
    load_regs(1);
    if (tid == 0) s_t2[0] = atomicAdd(&g_ticket, 1);   // ticket for chunk 0
    __syncthreads();

    for (int c = 0; c < nch; c++) {
        // grab next chunk's ticket (broadcast via end-of-chunk syncthreads)
        if (tid == 0 && c + 1 < nch) s_t2[(c + 1) & 1] = atomicAdd(&g_ticket, 1);

        if (c + 1 < nch) {
            convert_to(sm + ((c + 1) % 3) * BUFB, c + 1);
            if (c + 2 < nch) load_regs(c + 2);
        }

        // issue this chunk's copy loads AFTER the register-heavy convert:
        // live range spans only the MMA section below (ample to hide DRAM latency,
        // short enough to avoid spilling at the 128-reg cap).
        CopyTk ct;
        copy_load(pp, (long)s_t2[c & 1], ct);

        uint32_t bu = sb + (c % 3) * BUFB;
        #pragma unroll
        for (int ks = 0; ks < 2; ks++) {
            uint32_t ah[2][4], al[2][4], bh[4][2], bl[4][2];
            #pragma unroll
            for (int mt = 0; mt < 2; mt++) {
                uint32_t off = (uint32_t)(mbase + mt * 16 + (lane & 15)) * 64
                             + ks * 32 + (lane >> 4) * 16;
                ldsm4(ah[mt], bu + swz64(off));
                ldsm4(al[mt], bu + 4096 + swz64(off));
            }
            #pragma unroll
            for (int nt = 0; nt < 4; nt++) {
                uint32_t off = (uint32_t)(nbase + nt * 8 + (lane & 7)) * 64
                             + ks * 32 + ((lane >> 3) & 1) * 16;
                ldsm2(bh[nt], bu + 8192 + swz64(off));
                ldsm2(bl[nt], bu + 16384 + swz64(off));
            }
            #pragma unroll
            for (int mt = 0; mt < 2; mt++)
                #pragma unroll
                for (int nt = 0; nt < 4; nt++) {
                    mma16816(acc[mt][nt], ah[mt], bh[nt]);
                    mma16816(acc[mt][nt], al[mt], bh[nt]);
                    mma16816(acc[mt][nt], ah[mt], bl[nt]);
                }
        }
        // copy stores: loads have had the whole MMA section to land
        copy_store(ct);
        __syncthreads();
    }

    // secondary publishes its partial before the rendezvous
    if (!primary) {
        #pragma unroll
        for (int mt = 0; mt < 2; mt++)
            #pragma unroll
            for (int nt = 0; nt < 4; nt++) {
                int cl = nbase + nt * 8 + (lane & 3) * 2;
                #pragma unroll
                for (int h = 0; h < 2; h++) {
                    int r = mbase + mt * 16 + (lane >> 2) + h * 8;
                    float2 v = {acc[mt][nt][h * 2], acc[mt][nt][h * 2 + 1]};
                    *(float2*)(part + r * 128 + cl) = v;
                }
            }
    }

    barrier_on(mbar, 2);
    if (!primary) return;

    #pragma unroll
    for (int mt = 0; mt < 2; mt++)
        #pragma unroll
        for (int nt = 0; nt < 4; nt++) {
            int cl = nbase + nt * 8 + (lane & 3) * 2;
            int cc = n0 + cl;
            int gblk = ((n0 + nbase + nt * 8) * magic) >> 16;
            #pragma unroll
            for (int h = 0; h < 2; h++) {
                int r = mbase + mt * 16 + (lane >> 2) + h * 8;
                float2 pv = ldcg2(part + r * 128 + cl);
                float v0 = acc[mt][nt][h * 2 + 0] + pv.x + __ldg(bias + cc);
                float v1 = acc[mt][nt][h * 2 + 1] + pv.y + __ldg(bias + cc + 1);
                if (MODE <= 1) {
                    v0 = v0 / (1.f + __expf(-v0));
                    v1 = v1 / (1.f + __expf(-v1));
                }
                if (MODE == 1) {
                    float2 rv = ldcg2(A + (size_t)r * hid + cc);
                    v0 += rv.x; v1 += rv.y;
                }
                float2 o2 = {v0, v1};
                *(float2*)(O + (size_t)r * hid + cc) = o2;
                if (STATS) {
                    float ps = v0 + v1;
                    float q = v0 * v0 + v1 * v1;
                    ps += __shfl_xor_sync(0xffffffff, ps, 1);
                    q  += __shfl_xor_sync(0xffffffff, q, 1);
                    ps += __shfl_xor_sync(0xffffffff, ps, 2);
                    q  += __shfl_xor_sync(0xffffffff, q, 2);
                    if ((lane & 3) == 0) {
                        atomicAdd(ws_s + r * 32 + gblk, ps);
                        atomicAdd(ws_q + r * 32 + gblk, q);
                    }
                }
            }
        }
}

// ---------------- ticketed copy (dedicated CTAs + post-compute drain) ----------------
__device__ void copy_work(const Params& p, int* s_ticket) {
    while (true) {
        if (threadIdx.x == 0) *s_ticket = atomicAdd(&g_ticket, 4);
        __syncthreads();
        long t0 = *s_ticket;
        __syncthreads();
        if (t0 * SLOT4 >= N4T) break;
        // pipeline pairs: load 2 tickets, store 2 tickets
        #pragma unroll
        for (int j = 0; j < 4; j += 2) {
            CopyTk a, b;
            copy_load(p, t0 + j, a);
            copy_load(p, t0 + j + 1, b);
            copy_store(a);
            copy_store(b);
        }
    }
}

// ---------------- scatter ----------------
__device__ void scatter_all(float* __restrict__ out, int cid) {
    for (int c = cid; c < 80; c += NCTA) {
        int te = c / 40, rem = c % 40, b = rem / 5, r = rem % 5;
        int np = g_npos[b];
        if (!np) continue;
        int hid = te ? H2C : H1C;
        int t = (r < 4) ? r : 3;
        int chain = te * 4 + t;
        const float* tok = g_bufA + ch_off(chain);
        float* o = te ? out + OUT0_ELEMS + (size_t)b * SSV * H2C
                      : out + (size_t)b * SSV * H1C;
        int h4 = hid >> 2, tot = np * h4;
        for (int e = threadIdx.x; e < tot; e += NTHR) {
            int i = e / h4, c4 = e % h4;
            int s = (r < 4) ? (SSV - 1 - r * np - i) : (SSV - 5 * np + i);
            float4 v = __ldcg((const float4*)(tok + (size_t)(b * 16 + i) * hid) + c4);
            ((float4*)(o + (size_t)s * hid))[c4] = v;
        }
    }
}

// ---------------- kernels ----------------
__global__ void reset_kernel() {
    int idx = blockIdx.x * 256 + threadIdx.x;
    if (idx < 3 * 8 * 4096) { g_sum[idx] = 0.f; g_ss[idx] = 0.f; }
    if (idx < 640) g_mbar[idx] = 0;
    if (idx < 40) g_cbar[idx] = 0;
    if (idx == 40) { g_gbar = 0; g_ticket = 0; }
}

__global__ void __launch_bounds__(NTHR, 2) mega_kernel(Params p) {
    extern __shared__ char smraw[];
    __shared__ int s_ticket;
    __shared__ int s_t2[2];
    int cid = blockIdx.x, tid = threadIdx.x;

    if (cid >= NCOMP) {
        copy_work(p, &s_ticket);
        barrier_on(&g_gbar, NCTA);
        scatter_all(p.out, cid);
        return;
    }

    uint32_t sb0 = s2u(smraw);
    uint32_t sb = (sb0 + 1023) & ~1023u;
    char* sm = smraw + (sb - sb0);
    int lane = tid & 31, wid = tid >> 5;

    if (cid < 8 && wid == 0) {
        int b = cid, cnt = 0;
        for (int s = 0; s < 16; s++) {
            float v = 0.f;
            #pragma unroll
            for (int j = 0; j < 8; j++)
                v += fabsf(p.extra[((size_t)b * 16 + s) * 704 + 448 + lane * 8 + j]);
            #pragma unroll
            for (int o = 16; o > 0; o >>= 1)
                v += __shfl_xor_sync(0xffffffff, v, o);
            if (v > 1e-6f) cnt++;
        }
        if (lane == 0) g_npos[b] = cnt;
    }

    // decode: cid<160: te2 chains (4 x 40: kh x mt x nt = 2x2x10)
    //         160<=cid<256: te1 chains (4 x 24: 2x2x6)
    int chain, nt, mt, kh, hid, nc_chain, slot;
    if (cid < 160) {
        chain = 4 + cid / 40;
        int r = cid % 40;
        kh = r / 20; int rr = r % 20;
        mt = rr / 10; nt = rr % 10;
        hid = 1280; nc_chain = 40;
        slot = 48 + (chain - 4) * 20 + mt * 10 + nt;
    } else {
        int c2 = cid - 160;
        chain = c2 / 24;
        int r = c2 % 24;
        kh = r / 12; int rr = r % 12;
        mt = rr / 6; nt = rr % 6;
        hid = 768; nc_chain = 24;
        slot = chain * 12 + mt * 6 + nt;
    }
    int te = chain >> 2, t = chain & 3;
    int n0 = nt * 128, m0 = mt * 64;   // N-tile stride is 128 (R13-proven mapping)
    int magic = (hid == 768) ? 2731 : 1639;
    float inv_gs = 1.f / (float)(hid >> 5);
    size_t co = ch_off(chain);
    bool primary = (kh == 0);
    float* part = g_part + (size_t)slot * 8192;
    int* mb = g_mbar + slot * 5;
    int* cb = g_cbar + chain * 5;

    float* st_s0 = g_sum + (0 * 8 + chain) * 4096 + m0 * 32;
    float* st_q0 = g_ss  + (0 * 8 + chain) * 4096 + m0 * 32;
    float* st_s1 = g_sum + (1 * 8 + chain) * 4096 + m0 * 32;
    float* st_q1 = g_ss  + (1 * 8 + chain) * 4096 + m0 * 32;
    float* st_s2 = g_sum + (2 * 8 + chain) * 4096 + m0 * 32;
    float* st_q2 = g_ss  + (2 * 8 + chain) * 4096 + m0 * 32;

    int Kh_fc1 = 352, Kh = hid >> 1;
    float* bA = g_bufA + co + (size_t)m0 * hid;
    float* bB = g_bufB + co + (size_t)m0 * hid;

    run_stage<0, true>(sm, sb, p.extra + (size_t)m0 * 704, bA,
                       p.f1w[te] + (size_t)t * hid * 704, p.f1b[te] + t * hid,
                       nullptr, nullptr, nullptr, nullptr, st_s0, st_q0,
                       704, Kh_fc1, kh * Kh_fc1, hid, n0, magic, inv_gs,
                       part, mb + 0, primary, p, s_t2);
    barrier_on(cb + 0, nc_chain);

    {
        size_t wo = (size_t)(t * 3 + 0) * hid;
        run_stage<1, true>(sm, sb, bA, bB,
                           p.bw[te] + wo * hid, p.bb[te] + wo,
                           p.gg[te] + wo, p.gb[te] + wo, st_s0, st_q0, st_s1, st_q1,
                           hid, Kh, kh * Kh, hid, n0, magic, inv_gs,
                           part, mb + 1, primary, p, s_t2);
    }
    barrier_on(cb + 1, nc_chain);

    {
        size_t wo = (size_t)(t * 3 + 1) * hid;
        run_stage<1, true>(sm, sb, bB, bA,
                           p.bw[te] + wo * hid, p.bb[te] + wo,
                           p.gg[te] + wo, p.gb[te] + wo, st_s1, st_q1, st_s2, st_q2,
                           hid, Kh, kh * Kh, hid, n0, magic, inv_gs,
                           part, mb + 2, primary, p, s_t2);
    }
    barrier_on(cb + 2, nc_chain);

    {
        size_t wo = (size_t)(t * 3 + 2) * hid;
        run_stage<1, false>(sm, sb, bA, bB,
                            p.bw[te] + wo * hid, p.bb[te] + wo,
                            p.gg[te] + wo, p.gb[te] + wo, st_s2, st_q2, nullptr, nullptr,
                            hid, Kh, kh * Kh, hid, n0, magic, inv_gs,
                            part, mb + 3, primary, p, s_t2);
    }
    barrier_on(cb + 3, nc_chain);

    run_stage<2, false>(sm, sb, bB, bA,
                        p.ow[te] + (size_t)t * hid * hid, p.ob[te] + t * hid,
                        nullptr, nullptr, nullptr, nullptr, nullptr, nullptr,
                        hid, Kh, kh * Kh, hid, n0, magic, inv_gs,
                        part, mb + 4, primary, p, s_t2);

    copy_work(p, &s_ticket);
    barrier_on(&g_gbar, NCTA);
    scatter_all(p.out, cid);
}

// ---------------- launch ----------------
extern "C" void kernel_launch(void* const* d_in, const int* in_sizes, int n_in,
                              void* d_out, int out_size) {
    Params p;
    p.e0    = (const float*)d_in[0];
    p.e1    = (const float*)d_in[1];
    p.e2    = (const float*)d_in[2];
    p.extra = (const float*)d_in[3];
    p.f1w[0] = (const float*)d_in[4];  p.f1b[0] = (const float*)d_in[5];
    p.gg[0]  = (const float*)d_in[6];  p.gb[0]  = (const float*)d_in[7];
    p.bw[0]  = (const float*)d_in[8];  p.bb[0]  = (const float*)d_in[9];
    p.ow[0]  = (const float*)d_in[10]; p.ob[0]  = (const float*)d_in[11];
    p.f1w[1] = (const float*)d_in[12]; p.f1b[1] = (const float*)d_in[13];
    p.gg[1]  = (const float*)d_in[14]; p.gb[1]  = (const float*)d_in[15];
    p.bw[1]  = (const float*)d_in[16]; p.bb[1]  = (const float*)d_in[17];
    p.ow[1]  = (const float*)d_in[18]; p.ob[1]  = (const float*)d_in[19];
    p.out = (float*)d_out;

    cudaFuncSetAttribute(mega_kernel, cudaFuncAttributeMaxDynamicSharedMemorySize, SMEM_BYTES);

    reset_kernel<<<(3 * 8 * 4096 + 255) / 256, 256>>>();
    mega_kernel<<<NCTA, NTHR, SMEM_BYTES>>>(p);
}